// round 10
// baseline (speedup 1.0000x reference)
#include <cuda_runtime.h>
#include <cuda_bf16.h>
#include <cstdint>

// ---------------- problem constants (fixed shapes) ----------------
#define N_NODES 200000
#define N_EDGES 1000000
#define D_NODE  128
#define D_EDGE  64
#define HDIM    256
#define NGRAPH  512

#define MT 128                                   // rows per CTA-tile
#define NODE_TILES ((N_NODES + MT - 1) / MT)     // 1563 (last tile 64 rows)
#define EDGE_TILES ((N_EDGES + MT - 1) / MT)     // 7813 (last tile 64 rows)
#define NCTA  128                                // output columns per CTA (HDIM split in 2)

// ---------------- scratch (device globals; no allocation) ----------------
__device__ float d_S_node[NGRAPH * HDIM];
__device__ float d_S_edge[NGRAPH * HDIM];
__device__ int   d_cnt_node[NGRAPH];
__device__ int   d_cnt_edge[NGRAPH];
__device__ unsigned short d_eb[N_EDGES];     // graph id per edge
__device__ int   d_esorted[N_EDGES];         // edge ids sorted by graph
__device__ int   d_cursor[NGRAPH];
__device__ __nv_bfloat16 d_Wt_node[HDIM * D_NODE];  // [n][k]  (transposed, bf16)
__device__ __nv_bfloat16 d_Wt_edge[HDIM * D_EDGE];  // [n][k]

// ---------------- asm helpers ----------------
#define LDSM_X4(r0, r1, r2, r3, addr)                                          \
    asm volatile("ldmatrix.sync.aligned.m8n8.x4.shared.b16 {%0,%1,%2,%3}, [%4];" \
                 : "=r"(r0), "=r"(r1), "=r"(r2), "=r"(r3) : "r"(addr))

#define MMA16816(c0, c1, c2, c3, a0, a1, a2, a3, b0, b1)                       \
    asm volatile(                                                              \
        "mma.sync.aligned.m16n8k16.row.col.f32.bf16.bf16.f32 "                 \
        "{%0,%1,%2,%3}, {%4,%5,%6,%7}, {%8,%9}, {%0,%1,%2,%3};\n"              \
        : "+f"(c0), "+f"(c1), "+f"(c2), "+f"(c3)                               \
        : "r"(a0), "r"(a1), "r"(a2), "r"(a3), "r"(b0), "r"(b1))

// ---------------- launch #1: zero sums + weight transpose + histograms ----
// (count buffers pre-zeroed by cudaMemsetAsync — zeroing here would race)
__global__ void k_setup(const float* __restrict__ Wn1, const float* __restrict__ We1,
                        const int* __restrict__ batch_idx, const int* __restrict__ edge_src)
{
    const int b = blockIdx.x;
    const int tid = threadIdx.x;
    if (b < 64) {
        int i = b * 256 + tid;
        for (int j = i; j < HDIM * D_NODE; j += 64 * 256) {
            int n = j / D_NODE, k = j % D_NODE;
            d_Wt_node[j] = __float2bfloat16(Wn1[k * HDIM + n]);
        }
        for (int j = i; j < HDIM * D_EDGE; j += 64 * 256) {
            int n = j / D_EDGE, k = j % D_EDGE;
            d_Wt_edge[j] = __float2bfloat16(We1[k * HDIM + n]);
        }
    } else if (b < 128) {
        int i = (b - 64) * 256 + tid;
        for (int j = i; j < NGRAPH * HDIM; j += 64 * 256) { d_S_node[j] = 0.f; d_S_edge[j] = 0.f; }
    } else if (b < 328) {
        __shared__ int h[NGRAPH];
        for (int j = tid; j < NGRAPH; j += 256) h[j] = 0;
        __syncthreads();
        int i = (b - 128) * 256 + tid;
        for (int n = i; n < N_NODES; n += 200 * 256) atomicAdd(&h[batch_idx[n]], 1);
        __syncthreads();
        for (int j = tid; j < NGRAPH; j += 256)
            if (h[j]) atomicAdd(&d_cnt_node[j], h[j]);
    } else {
        __shared__ int h[NGRAPH];
        for (int j = tid; j < NGRAPH; j += 256) h[j] = 0;
        __syncthreads();
        int i = (b - 328) * 256 + tid;
        for (int e = i; e < N_EDGES; e += 512 * 256) {
            int g = batch_idx[edge_src[e]];
            d_eb[e] = (unsigned short)g;
            atomicAdd(&h[g], 1);
        }
        __syncthreads();
        for (int j = tid; j < NGRAPH; j += 256)
            if (h[j]) atomicAdd(&d_cnt_edge[j], h[j]);
    }
}

// ---------------- launch #2: exclusive prefix sum of edge counts ----------
__global__ void k_scan() {
    __shared__ int wsum[16];
    int tid = threadIdx.x;
    int lane = tid & 31, w = tid >> 5;
    int v = d_cnt_edge[tid];
    int s = v;
    #pragma unroll
    for (int o = 1; o < 32; o <<= 1) {
        int t = __shfl_up_sync(0xffffffffu, s, o);
        if (lane >= o) s += t;
    }
    if (lane == 31) wsum[w] = s;
    __syncthreads();
    if (tid == 0) {
        int run = 0;
        for (int i = 0; i < 16; i++) { int t = wsum[i]; wsum[i] = run; run += t; }
    }
    __syncthreads();
    d_cursor[tid] = s + wsum[w] - v;   // exclusive
}

// ---------------- launch #3: counting-sort scatter of edge ids ------------
__global__ void k_scatter() {
    int i = blockIdx.x * blockDim.x + threadIdx.x;
    int stride = gridDim.x * blockDim.x;
    for (int e = i; e < N_EDGES; e += stride) {
        int g = (int)d_eb[e];
        int p = atomicAdd(&d_cursor[g], 1);
        d_esorted[p] = e;
    }
}

// ---------------- first-layer GEMM + segmented column sums ----------------
// 512 threads = 16 warps: wm = (w&3)*32 (4 M-slices), wn = (w>>2)*32 (4 N-slices).
// CTA tile 128 rows x 128 cols (nhalf = blockIdx&1); warp tile 32x32.
// mma m16n8k16 bf16, fp32 accum, LDSM fragment loads.
// Epilogue: per-graph register reduce (shfl over gID) + direct global atomics.
template<int K, int KPAD, int KSTEPS, int NITER, bool IS_EDGE>
__device__ __forceinline__ void gemm_phase(
    const float* __restrict__ A_gmem, const float* __restrict__ bias_g,
    const __nv_bfloat16* __restrict__ Wt_g,
    const int* __restrict__ batch_idx, int n_rows_total, int n_tiles,
    float* __restrict__ S_out, char* smem, uint32_t sbase)
{
    // smem: Ws[128][KPAD] | As[128][KPAD] | gid[128] | es[128] | bias[128]
    constexpr int WS_BYTES = NCTA * KPAD * 2;
    constexpr int AS_BYTES = MT * KPAD * 2;
    __nv_bfloat16* Ws = (__nv_bfloat16*)(smem);
    __nv_bfloat16* As = (__nv_bfloat16*)(smem + WS_BYTES);
    int*   gid_s  = (int*)(smem + WS_BYTES + AS_BYTES);
    int*   es_s   = (int*)(smem + WS_BYTES + AS_BYTES + 512);
    float* bias_s = (float*)(smem + WS_BYTES + AS_BYTES + 1024);

    const int tid = threadIdx.x;
    const int nbase = (blockIdx.x & 1) * NCTA;   // fixed per CTA (grid stride is even)

    // load this CTA's half of the transposed weights [n][k] -> padded smem rows
    const uint32_t* Wg32 = (const uint32_t*)Wt_g;
    for (int j = tid; j < NCTA * K / 2; j += 512) {
        int n = j / (K / 2), k2 = j % (K / 2);
        *(uint32_t*)&Ws[n * KPAD + 2 * k2] = Wg32[(nbase + n) * (K / 2) + k2];
    }
    if (tid < NCTA) bias_s[tid] = bias_g[nbase + tid];
    __syncthreads();

    const int lane = tid & 31, warp = tid >> 5;
    const int wm = (warp & 3) * 32;
    const int wn = (warp >> 2) * 32;
    const int gID = lane >> 2, tig = lane & 3;

    // ldmatrix lane addresses (byte offsets in smem window)
    const uint32_t a_addr0 = sbase + WS_BYTES +
        (uint32_t)(((wm + (lane & 15)) * KPAD + ((lane >> 4) << 3)) * 2);
    const uint32_t a_addr1 = a_addr0 + (uint32_t)(16 * KPAD * 2);
    const int brow = (lane & 7) + ((lane >> 4) << 3);
    const int bkof = ((lane >> 3) & 1) << 3;
    const uint32_t b_addr0 = sbase +
        (uint32_t)(((wn + brow) * KPAD + bkof) * 2);

    const int QK = K / 4;   // float4 per row

    for (int b = blockIdx.x; b < 2 * n_tiles; b += gridDim.x) {
        const int t = b >> 1;
        const int r0 = t * MT;
        int rows = n_rows_total - r0; if (rows > MT) rows = MT;

        __syncthreads();   // protect gid_s/es_s/As from previous iteration readers
        if (tid < MT) {
            int e = -1, gi = -1;
            if (tid < rows) {
                if (IS_EDGE) { e = d_esorted[r0 + tid]; gi = (int)d_eb[e]; }
                else         { e = r0 + tid;            gi = batch_idx[e]; }
            }
            es_s[tid]  = e;
            gid_s[tid] = gi;
        }
        __syncthreads();

        // ---- gather A tile in chunks of 4 float4 (MLP=4) ----
        #pragma unroll
        for (int base = 0; base < NITER; base += 4) {
            float4 v[4];
            #pragma unroll
            for (int i = 0; i < 4; i++) {
                int j = tid + (base + i) * 512;
                int r = j / QK, q = j % QK;
                int e = es_s[r];
                v[i] = (e >= 0) ? *(const float4*)(A_gmem + (size_t)e * K + q * 4)
                                : make_float4(0.f, 0.f, 0.f, 0.f);
            }
            #pragma unroll
            for (int i = 0; i < 4; i++) {
                int j = tid + (base + i) * 512;
                int r = j / QK, q = j % QK;
                __nv_bfloat162 p0 = __float22bfloat162_rn(make_float2(v[i].x, v[i].y));
                __nv_bfloat162 p1 = __float22bfloat162_rn(make_float2(v[i].z, v[i].w));
                *(__nv_bfloat162*)&As[r * KPAD + q * 4]     = p0;
                *(__nv_bfloat162*)&As[r * KPAD + q * 4 + 2] = p1;
            }
        }
        __syncthreads();

        // row gids for this lane's fragment rows
        int gr0[2], gr1[2];
        #pragma unroll
        for (int mf = 0; mf < 2; mf++) {
            gr0[mf] = gid_s[wm + mf * 16 + gID];
            gr1[mf] = gid_s[wm + mf * 16 + gID + 8];
        }
        const int g_lo = gid_s[0];
        const int g_hi = gid_s[rows - 1];

        // ---- mainloop (ldmatrix + mma) ----
        float c[2][4][4];
        #pragma unroll
        for (int mf = 0; mf < 2; mf++)
            #pragma unroll
            for (int nf = 0; nf < 4; nf++)
                #pragma unroll
                for (int r = 0; r < 4; r++) c[mf][nf][r] = 0.f;

        #pragma unroll
        for (int ks = 0; ks < KSTEPS; ks++) {
            const uint32_t koff = (uint32_t)(ks * 16 * 2);
            uint32_t a[2][4];
            LDSM_X4(a[0][0], a[0][1], a[0][2], a[0][3], a_addr0 + koff);
            LDSM_X4(a[1][0], a[1][1], a[1][2], a[1][3], a_addr1 + koff);
            #pragma unroll
            for (int nfp = 0; nfp < 2; nfp++) {
                uint32_t b0, b1, b2, b3;
                LDSM_X4(b0, b1, b2, b3,
                        b_addr0 + (uint32_t)(nfp * 16 * KPAD * 2) + koff);
                const int nf = 2 * nfp;
                MMA16816(c[0][nf][0], c[0][nf][1], c[0][nf][2], c[0][nf][3],
                         a[0][0], a[0][1], a[0][2], a[0][3], b0, b1);
                MMA16816(c[1][nf][0], c[1][nf][1], c[1][nf][2], c[1][nf][3],
                         a[1][0], a[1][1], a[1][2], a[1][3], b0, b1);
                MMA16816(c[0][nf+1][0], c[0][nf+1][1], c[0][nf+1][2], c[0][nf+1][3],
                         a[0][0], a[0][1], a[0][2], a[0][3], b2, b3);
                MMA16816(c[1][nf+1][0], c[1][nf+1][1], c[1][nf+1][2], c[1][nf+1][3],
                         a[1][0], a[1][1], a[1][2], a[1][3], b2, b3);
            }
        }

        // ---- bias + relu ----
        #pragma unroll
        for (int nf = 0; nf < 4; nf++) {
            float b0 = bias_s[wn + nf * 8 + 2 * tig];
            float b1 = bias_s[wn + nf * 8 + 2 * tig + 1];
            #pragma unroll
            for (int mf = 0; mf < 2; mf++) {
                c[mf][nf][0] = fmaxf(c[mf][nf][0] + b0, 0.f);
                c[mf][nf][1] = fmaxf(c[mf][nf][1] + b1, 0.f);
                c[mf][nf][2] = fmaxf(c[mf][nf][2] + b0, 0.f);
                c[mf][nf][3] = fmaxf(c[mf][nf][3] + b1, 0.f);
            }
        }

        // ---- per-graph register reduce + direct global atomics ----
        // rows with gid -1 (padding) never match any g in [g_lo, g_hi]
        for (int g = g_lo; g <= g_hi; ++g) {
            #pragma unroll
            for (int nf = 0; nf < 4; nf++) {
                float s0 = 0.f, s1 = 0.f;
                #pragma unroll
                for (int mf = 0; mf < 2; mf++) {
                    if (gr0[mf] == g) { s0 += c[mf][nf][0]; s1 += c[mf][nf][1]; }
                    if (gr1[mf] == g) { s0 += c[mf][nf][2]; s1 += c[mf][nf][3]; }
                }
                #pragma unroll
                for (int o = 4; o <= 16; o <<= 1) {
                    s0 += __shfl_xor_sync(0xffffffffu, s0, o);
                    s1 += __shfl_xor_sync(0xffffffffu, s1, o);
                }
                if (lane < 4) {
                    float* dst = &S_out[g * HDIM + nbase + wn + nf * 8 + 2 * lane];
                    atomicAdd(dst,     s0);
                    atomicAdd(dst + 1, s1);
                }
            }
        }
    }
}

#define SMEM_NODE ((NCTA + MT) * (D_NODE + 8) * 2 + 1536)   // 71168
#define SMEM_EDGE ((NCTA + MT) * (D_EDGE + 8) * 2 + 1536)   // 38400

// ---------------- launch #4: edge GEMM (profiled slot) --------------------
__global__ void __launch_bounds__(512, 2)
k_gemm_edge(const float* __restrict__ edge_attr, const float* __restrict__ be1)
{
    extern __shared__ char smem[];
    uint32_t sbase = (uint32_t)__cvta_generic_to_shared(smem);
    gemm_phase<D_EDGE, D_EDGE + 8, D_EDGE / 16, MT * (D_EDGE / 4) / 512, true>(
        edge_attr, be1, d_Wt_edge, nullptr, N_EDGES, EDGE_TILES, d_S_edge, smem, sbase);
}

// ---------------- launch #5: node GEMM -------------------------------------
__global__ void __launch_bounds__(512, 2)
k_gemm_node(const float* __restrict__ x, const int* __restrict__ batch_idx,
            const float* __restrict__ bn1)
{
    extern __shared__ char smem[];
    uint32_t sbase = (uint32_t)__cvta_generic_to_shared(smem);
    gemm_phase<D_NODE, D_NODE + 8, D_NODE / 16, MT * (D_NODE / 4) / 512, false>(
        x, bn1, d_Wt_node, batch_idx, N_NODES, NODE_TILES, d_S_node, smem, sbase);
}

// ---------------- launch #6: means -> layer-2 -> combine ------------------
__global__ void __launch_bounds__(256)
k_finalize(const float* __restrict__ Wn2, const float* __restrict__ bn2,
           const float* __restrict__ We2, const float* __restrict__ be2,
           const float* __restrict__ Wc,  const float* __restrict__ bc,
           float* __restrict__ out)
{
    __shared__ float mn[8][HDIM], me[8][HDIM], gr[8][HDIM];
    __shared__ int fn[8], fe[8];
    const int tid = threadIdx.x;
    const int gbase = blockIdx.x * 8;

    #pragma unroll
    for (int gg = 0; gg < 8; gg++) {
        int g = gbase + gg;
        int cn = d_cnt_node[g], ce = d_cnt_edge[g];
        if (tid == 0) { fn[gg] = cn; fe[gg] = ce; }
        mn[gg][tid] = (cn > 0) ? d_S_node[g * HDIM + tid] / (float)cn : 0.f;
        me[gg][tid] = (ce > 0) ? d_S_edge[g * HDIM + tid] / (float)ce : 0.f;
    }
    __syncthreads();

    float an[8], ae[8];
    #pragma unroll
    for (int gg = 0; gg < 8; gg++) { an[gg] = 0.f; ae[gg] = 0.f; }
    for (int j = 0; j < HDIM; j++) {
        float w1 = Wn2[j * HDIM + tid];
        float w2 = We2[j * HDIM + tid];
        #pragma unroll
        for (int gg = 0; gg < 8; gg++) {
            an[gg] += mn[gg][j] * w1;
            ae[gg] += me[gg][j] * w2;
        }
    }
    float b2n = bn2[tid], b2e = be2[tid];
    #pragma unroll
    for (int gg = 0; gg < 8; gg++) {
        float nr = (fn[gg] > 0) ? an[gg] + b2n : 0.f;
        float er = (fe[gg] > 0) ? ae[gg] + b2e : 0.f;
        gr[gg][tid] = nr + er;
    }
    __syncthreads();

    float ao[8];
    #pragma unroll
    for (int gg = 0; gg < 8; gg++) ao[gg] = 0.f;
    for (int j = 0; j < HDIM; j++) {
        float w = Wc[j * HDIM + tid];
        #pragma unroll
        for (int gg = 0; gg < 8; gg++) ao[gg] += gr[gg][j] * w;
    }
    float bcv = bc[tid];
    #pragma unroll
    for (int gg = 0; gg < 8; gg++)
        out[(gbase + gg) * HDIM + tid] = ao[gg] + bcv;
}

// ---------------- launch ----------------
extern "C" void kernel_launch(void* const* d_in, const int* in_sizes, int n_in,
                              void* d_out, int out_size)
{
    const float* x         = (const float*)d_in[0];
    const float* edge_attr = (const float*)d_in[1];
    const int*   batch_idx = (const int*)d_in[2];
    const int*   edge_src  = (const int*)d_in[3];
    const float* Wn1 = (const float*)d_in[4];
    const float* bn1 = (const float*)d_in[5];
    const float* Wn2 = (const float*)d_in[6];
    const float* bn2 = (const float*)d_in[7];
    const float* We1 = (const float*)d_in[8];
    const float* be1 = (const float*)d_in[9];
    const float* We2 = (const float*)d_in[10];
    const float* be2 = (const float*)d_in[11];
    const float* Wc  = (const float*)d_in[12];
    const float* bc  = (const float*)d_in[13];
    float* out = (float*)d_out;

    (void)in_sizes; (void)n_in; (void)out_size;

    cudaFuncSetAttribute(k_gemm_node, cudaFuncAttributeMaxDynamicSharedMemorySize, SMEM_NODE);
    cudaFuncSetAttribute(k_gemm_edge, cudaFuncAttributeMaxDynamicSharedMemorySize, SMEM_EDGE);

    // zero the histogram counters before k_setup's atomics
    // (memset nodes on the capture stream — not kernel launches)
    void* p_cn = nullptr; void* p_ce = nullptr;
    cudaGetSymbolAddress(&p_cn, d_cnt_node);
    cudaGetSymbolAddress(&p_ce, d_cnt_edge);
    cudaMemsetAsync(p_cn, 0, NGRAPH * sizeof(int));
    cudaMemsetAsync(p_ce, 0, NGRAPH * sizeof(int));

    k_setup<<<840, 256>>>(Wn1, We1, batch_idx, edge_src);              // kernel #1
    k_scan<<<1, 512>>>();                                              // #2
    k_scatter<<<512, 256>>>();                                         // #3
    k_gemm_edge<<<296, 512, SMEM_EDGE>>>(edge_attr, be1);              // #4 (profiled)
    k_gemm_node<<<296, 512, SMEM_NODE>>>(x, batch_idx, bn1);           // #5
    k_finalize<<<64, 256>>>(Wn2, bn2, We2, be2, Wc, bc, out);          // #6
}

// round 11
// speedup vs baseline: 1.0422x; 1.0422x over previous
#include <cuda_runtime.h>
#include <cuda_bf16.h>
#include <cstdint>

// ---------------- problem constants (fixed shapes) ----------------
#define N_NODES 200000
#define N_EDGES 1000000
#define D_NODE  128
#define D_EDGE  64
#define HDIM    256
#define NGRAPH  512

#define MTILE 64
#define NODE_TILES (N_NODES / MTILE)   // 3125 (exact)
#define EDGE_TILES (N_EDGES / MTILE)   // 15625 (exact)
#define NCTA  128                      // output columns per CTA (HDIM split in 2)

// ---------------- scratch (device globals; no allocation) ----------------
__device__ float d_S_node[NGRAPH * HDIM];
__device__ float d_S_edge[NGRAPH * HDIM];
__device__ int   d_cnt_node[NGRAPH];
__device__ int   d_cnt_edge[NGRAPH];
__device__ unsigned short d_eb[N_EDGES];     // graph id per edge
__device__ int   d_esorted[N_EDGES];         // edge ids sorted by graph
__device__ int   d_cursor[NGRAPH];
__device__ __nv_bfloat16 d_Wt_node[HDIM * D_NODE];  // [n][k]  (transposed, bf16)
__device__ __nv_bfloat16 d_Wt_edge[HDIM * D_EDGE];  // [n][k]

// ---------------- asm helpers ----------------
#define LDSM_X4(r0, r1, r2, r3, addr)                                          \
    asm volatile("ldmatrix.sync.aligned.m8n8.x4.shared.b16 {%0,%1,%2,%3}, [%4];" \
                 : "=r"(r0), "=r"(r1), "=r"(r2), "=r"(r3) : "r"(addr))

#define MMA16816(c0, c1, c2, c3, a0, a1, a2, a3, b0, b1)                       \
    asm volatile(                                                              \
        "mma.sync.aligned.m16n8k16.row.col.f32.bf16.bf16.f32 "                 \
        "{%0,%1,%2,%3}, {%4,%5,%6,%7}, {%8,%9}, {%0,%1,%2,%3};\n"              \
        : "+f"(c0), "+f"(c1), "+f"(c2), "+f"(c3)                               \
        : "r"(a0), "r"(a1), "r"(a2), "r"(a3), "r"(b0), "r"(b1))

// ---------------- launch #1: zero sums + weight transpose + histograms ----
// (count buffers pre-zeroed by cudaMemsetAsync — zeroing here would race)
__global__ void k_setup(const float* __restrict__ Wn1, const float* __restrict__ We1,
                        const int* __restrict__ batch_idx, const int* __restrict__ edge_src)
{
    const int b = blockIdx.x;
    const int tid = threadIdx.x;
    if (b < 64) {
        int i = b * 256 + tid;
        for (int j = i; j < HDIM * D_NODE; j += 64 * 256) {
            int n = j / D_NODE, k = j % D_NODE;
            d_Wt_node[j] = __float2bfloat16(Wn1[k * HDIM + n]);
        }
        for (int j = i; j < HDIM * D_EDGE; j += 64 * 256) {
            int n = j / D_EDGE, k = j % D_EDGE;
            d_Wt_edge[j] = __float2bfloat16(We1[k * HDIM + n]);
        }
    } else if (b < 128) {
        int i = (b - 64) * 256 + tid;
        for (int j = i; j < NGRAPH * HDIM; j += 64 * 256) { d_S_node[j] = 0.f; d_S_edge[j] = 0.f; }
    } else if (b < 328) {
        __shared__ int h[NGRAPH];
        for (int j = tid; j < NGRAPH; j += 256) h[j] = 0;
        __syncthreads();
        int i = (b - 128) * 256 + tid;
        for (int n = i; n < N_NODES; n += 200 * 256) atomicAdd(&h[batch_idx[n]], 1);
        __syncthreads();
        for (int j = tid; j < NGRAPH; j += 256)
            if (h[j]) atomicAdd(&d_cnt_node[j], h[j]);
    } else {
        __shared__ int h[NGRAPH];
        for (int j = tid; j < NGRAPH; j += 256) h[j] = 0;
        __syncthreads();
        int i = (b - 328) * 256 + tid;
        for (int e = i; e < N_EDGES; e += 512 * 256) {
            int g = batch_idx[edge_src[e]];
            d_eb[e] = (unsigned short)g;
            atomicAdd(&h[g], 1);
        }
        __syncthreads();
        for (int j = tid; j < NGRAPH; j += 256)
            if (h[j]) atomicAdd(&d_cnt_edge[j], h[j]);
    }
}

// ---------------- launch #2: exclusive prefix sum of edge counts ----------
__global__ void k_scan() {
    __shared__ int wsum[16];
    int tid = threadIdx.x;
    int lane = tid & 31, w = tid >> 5;
    int v = d_cnt_edge[tid];
    int s = v;
    #pragma unroll
    for (int o = 1; o < 32; o <<= 1) {
        int t = __shfl_up_sync(0xffffffffu, s, o);
        if (lane >= o) s += t;
    }
    if (lane == 31) wsum[w] = s;
    __syncthreads();
    if (tid == 0) {
        int run = 0;
        for (int i = 0; i < 16; i++) { int t = wsum[i]; wsum[i] = run; run += t; }
    }
    __syncthreads();
    d_cursor[tid] = s + wsum[w] - v;   // exclusive
}

// ---------------- launch #3: counting-sort scatter of edge ids ------------
__global__ void k_scatter() {
    int i = blockIdx.x * blockDim.x + threadIdx.x;
    int stride = gridDim.x * blockDim.x;
    for (int e = i; e < N_EDGES; e += stride) {
        int g = (int)d_eb[e];
        int p = atomicAdd(&d_cursor[g], 1);
        d_esorted[p] = e;
    }
}

// ================= launch #4: EDGE GEMM, software-pipelined ================
// 256 threads = 8 warps, CTA tile 64 rows x 128 cols (nhalf = blockIdx&1).
// Double-buffered As + register prefetch of next tile's gather; 1 barrier/tile.
#define EKPAD 72
#define E_AS_OFF 18432                       // Ws = 128*72*2
#define E_ASB    9216                        // one As buffer = 64*72*2
#define E_GID    36864                       // 2 x 64 ints
#define E_ES     37376                       // 2 x 64 ints
#define E_BIAS   37888                       // 128 floats
#define E_SMEM   38400

__global__ void __launch_bounds__(256, 3)
k_gemm_edge(const float* __restrict__ edge_attr, const float* __restrict__ be1)
{
    extern __shared__ char smem[];
    uint32_t sbase = (uint32_t)__cvta_generic_to_shared(smem);
    __nv_bfloat16* Ws = (__nv_bfloat16*)smem;
    __nv_bfloat16* As = (__nv_bfloat16*)(smem + E_AS_OFF);  // [2][64*72]
    int*   gid_s  = (int*)(smem + E_GID);                   // [2][64]
    int*   es_s   = (int*)(smem + E_ES);                    // [2][64]
    float* bias_s = (float*)(smem + E_BIAS);

    const int tid = threadIdx.x;
    const int nbase = (blockIdx.x & 1) * NCTA;   // grid stride even -> fixed per CTA

    // weights [n][k], k=64 padded to 72
    const uint32_t* Wg32 = (const uint32_t*)d_Wt_edge;
    for (int j = tid; j < NCTA * 32; j += 256) {
        int n = j >> 5, k2 = j & 31;
        *(uint32_t*)&Ws[n * EKPAD + 2 * k2] = Wg32[(nbase + n) * 32 + k2];
    }
    if (tid < NCTA) bias_s[tid] = be1[nbase + tid];

    const int lane = tid & 31, warp = tid >> 5;
    const int wm = (warp & 1) * 32;
    const int wn = (warp >> 1) * 32;
    const int gID = lane >> 2, tig = lane & 3;

    const uint32_t a_off = (uint32_t)(((wm + (lane & 15)) * EKPAD + ((lane >> 4) << 3)) * 2);
    const int brow = (lane & 7) + ((lane >> 4) << 3);
    const int bkof = ((lane >> 3) & 1) << 3;
    const uint32_t b_addr0 = sbase + (uint32_t)(((wn + brow) * EKPAD + bkof) * 2);

    const int NB = 2 * EDGE_TILES;     // 31250
    const int stride = gridDim.x;

    // ---- prologue: stage first tile into buffer 0 ----
    {
        int r0 = (blockIdx.x >> 1) * MTILE;
        if (tid < MTILE) {
            int e = d_esorted[r0 + tid];
            es_s[tid]  = e;
            gid_s[tid] = (int)d_eb[e];
        }
    }
    __syncthreads();
    int gr0c[2], gr1c[2];
    gr0c[0] = gid_s[wm + gID];       gr0c[1] = gid_s[wm + 16 + gID];
    gr1c[0] = gid_s[wm + gID + 8];   gr1c[1] = gid_s[wm + 16 + gID + 8];
    int glo_c = gid_s[0], ghi_c = gid_s[MTILE - 1];
    {
        float4 v[4];
        #pragma unroll
        for (int i = 0; i < 4; i++) {
            int j = tid + i * 256;
            int r = j >> 4, qq = j & 15;
            v[i] = *(const float4*)(edge_attr + (size_t)es_s[r] * 64 + qq * 4);
        }
        #pragma unroll
        for (int i = 0; i < 4; i++) {
            int j = tid + i * 256;
            int r = j >> 4, qq = j & 15;
            __nv_bfloat162 p0 = __float22bfloat162_rn(make_float2(v[i].x, v[i].y));
            __nv_bfloat162 p1 = __float22bfloat162_rn(make_float2(v[i].z, v[i].w));
            *(__nv_bfloat162*)&As[r * EKPAD + qq * 4]     = p0;
            *(__nv_bfloat162*)&As[r * EKPAD + qq * 4 + 2] = p1;
        }
    }

    int p = 0;
    for (int b = blockIdx.x; b < NB; b += stride) {
        const int q = p ^ 1;
        const int bn = b + stride;
        const bool has_next = (bn < NB);

        // stage next tile's indices into buffer q (before the barrier)
        if (has_next && tid < MTILE) {
            int r0n = (bn >> 1) * MTILE;
            int e = d_esorted[r0n + tid];
            es_s[q * MTILE + tid]  = e;
            gid_s[q * MTILE + tid] = (int)d_eb[e];
        }
        __syncthreads();   // As[p] (prev STS) + es/gid[q] visible; all reads of As[q] done

        // prefetch next tile's gid fragments into registers
        int gr0n[2] = {0, 0}, gr1n[2] = {0, 0}, glo_n = 0, ghi_n = -1;
        if (has_next) {
            gr0n[0] = gid_s[q * MTILE + wm + gID];
            gr0n[1] = gid_s[q * MTILE + wm + 16 + gID];
            gr1n[0] = gid_s[q * MTILE + wm + gID + 8];
            gr1n[1] = gid_s[q * MTILE + wm + 16 + gID + 8];
            glo_n = gid_s[q * MTILE];
            ghi_n = gid_s[q * MTILE + MTILE - 1];
        }

        // issue next tile's gather LDGs (results land after the MMA below)
        float4 v[4];
        if (has_next) {
            #pragma unroll
            for (int i = 0; i < 4; i++) {
                int j = tid + i * 256;
                int r = j >> 4, qq = j & 15;
                v[i] = *(const float4*)(edge_attr + (size_t)es_s[q * MTILE + r] * 64 + qq * 4);
            }
        }

        // ---- mainloop on As[p] ----
        const uint32_t a_base = sbase + E_AS_OFF + (uint32_t)(p * E_ASB) + a_off;
        float c[2][4][4];
        #pragma unroll
        for (int mf = 0; mf < 2; mf++)
            #pragma unroll
            for (int nf = 0; nf < 4; nf++)
                #pragma unroll
                for (int r = 0; r < 4; r++) c[mf][nf][r] = 0.f;

        #pragma unroll
        for (int ks = 0; ks < 4; ks++) {
            const uint32_t koff = (uint32_t)(ks * 32);
            uint32_t a[2][4];
            LDSM_X4(a[0][0], a[0][1], a[0][2], a[0][3], a_base + koff);
            LDSM_X4(a[1][0], a[1][1], a[1][2], a[1][3], a_base + 16 * EKPAD * 2 + koff);
            #pragma unroll
            for (int nfp = 0; nfp < 2; nfp++) {
                uint32_t b0, b1, b2, b3;
                LDSM_X4(b0, b1, b2, b3,
                        b_addr0 + (uint32_t)(nfp * 16 * EKPAD * 2) + koff);
                const int nf = 2 * nfp;
                MMA16816(c[0][nf][0], c[0][nf][1], c[0][nf][2], c[0][nf][3],
                         a[0][0], a[0][1], a[0][2], a[0][3], b0, b1);
                MMA16816(c[1][nf][0], c[1][nf][1], c[1][nf][2], c[1][nf][3],
                         a[1][0], a[1][1], a[1][2], a[1][3], b0, b1);
                MMA16816(c[0][nf+1][0], c[0][nf+1][1], c[0][nf+1][2], c[0][nf+1][3],
                         a[0][0], a[0][1], a[0][2], a[0][3], b2, b3);
                MMA16816(c[1][nf+1][0], c[1][nf+1][1], c[1][nf+1][2], c[1][nf+1][3],
                         a[1][0], a[1][1], a[1][2], a[1][3], b2, b3);
            }
        }

        // ---- bias + relu ----
        #pragma unroll
        for (int nf = 0; nf < 4; nf++) {
            float b0 = bias_s[wn + nf * 8 + 2 * tig];
            float b1 = bias_s[wn + nf * 8 + 2 * tig + 1];
            #pragma unroll
            for (int mf = 0; mf < 2; mf++) {
                c[mf][nf][0] = fmaxf(c[mf][nf][0] + b0, 0.f);
                c[mf][nf][1] = fmaxf(c[mf][nf][1] + b1, 0.f);
                c[mf][nf][2] = fmaxf(c[mf][nf][2] + b0, 0.f);
                c[mf][nf][3] = fmaxf(c[mf][nf][3] + b1, 0.f);
            }
        }

        // ---- per-graph register reduce + global atomics ----
        for (int g = glo_c; g <= ghi_c; ++g) {
            #pragma unroll
            for (int nf = 0; nf < 4; nf++) {
                float s0 = 0.f, s1 = 0.f;
                #pragma unroll
                for (int mf = 0; mf < 2; mf++) {
                    if (gr0c[mf] == g) { s0 += c[mf][nf][0]; s1 += c[mf][nf][1]; }
                    if (gr1c[mf] == g) { s0 += c[mf][nf][2]; s1 += c[mf][nf][3]; }
                }
                #pragma unroll
                for (int o = 4; o <= 16; o <<= 1) {
                    s0 += __shfl_xor_sync(0xffffffffu, s0, o);
                    s1 += __shfl_xor_sync(0xffffffffu, s1, o);
                }
                if (lane < 4) {
                    float* dst = &d_S_edge[g * HDIM + nbase + wn + nf * 8 + 2 * lane];
                    atomicAdd(dst,     s0);
                    atomicAdd(dst + 1, s1);
                }
            }
        }

        // ---- store prefetched tile into As[q] ----
        if (has_next) {
            #pragma unroll
            for (int i = 0; i < 4; i++) {
                int j = tid + i * 256;
                int r = j >> 4, qq = j & 15;
                __nv_bfloat162 p0 = __float22bfloat162_rn(make_float2(v[i].x, v[i].y));
                __nv_bfloat162 p1 = __float22bfloat162_rn(make_float2(v[i].z, v[i].w));
                *(__nv_bfloat162*)&As[q * (E_ASB / 2) + r * EKPAD + qq * 4]     = p0;
                *(__nv_bfloat162*)&As[q * (E_ASB / 2) + r * EKPAD + qq * 4 + 2] = p1;
            }
        }

        gr0c[0] = gr0n[0]; gr0c[1] = gr0n[1];
        gr1c[0] = gr1n[0]; gr1c[1] = gr1n[1];
        glo_c = glo_n; ghi_c = ghi_n;
        p = q;
    }
}

// ================= launch #5: NODE GEMM (R7 config, measured 70.9us) ======
template<int K, int KPAD, int KSTEPS, int NITER>
__device__ __forceinline__ void node_gemm_phase(
    const float* __restrict__ A_gmem, const float* __restrict__ bias_g,
    const __nv_bfloat16* __restrict__ Wt_g,
    const int* __restrict__ batch_idx, int n_tiles,
    float* __restrict__ S_out, char* smem, uint32_t sbase)
{
    constexpr int WS_BYTES = NCTA * KPAD * 2;
    constexpr int AS_BYTES = MTILE * KPAD * 2;
    __nv_bfloat16* Ws = (__nv_bfloat16*)(smem);
    __nv_bfloat16* As = (__nv_bfloat16*)(smem + WS_BYTES);
    int*   gid_s  = (int*)(smem + WS_BYTES + AS_BYTES);
    float* bias_s = (float*)(smem + WS_BYTES + AS_BYTES + 512);

    const int tid = threadIdx.x;
    const int nbase = (blockIdx.x & 1) * NCTA;

    const uint32_t* Wg32 = (const uint32_t*)Wt_g;
    for (int j = tid; j < NCTA * K / 2; j += 256) {
        int n = j / (K / 2), k2 = j % (K / 2);
        *(uint32_t*)&Ws[n * KPAD + 2 * k2] = Wg32[(nbase + n) * (K / 2) + k2];
    }
    if (tid < NCTA) bias_s[tid] = bias_g[nbase + tid];
    __syncthreads();

    const int lane = tid & 31, warp = tid >> 5;
    const int wm = (warp & 1) * 32;
    const int wn = (warp >> 1) * 32;
    const int gID = lane >> 2, tig = lane & 3;

    const uint32_t a_addr0 = sbase + WS_BYTES +
        (uint32_t)(((wm + (lane & 15)) * KPAD + ((lane >> 4) << 3)) * 2);
    const uint32_t a_addr1 = a_addr0 + (uint32_t)(16 * KPAD * 2);
    const int brow = (lane & 7) + ((lane >> 4) << 3);
    const int bkof = ((lane >> 3) & 1) << 3;
    const uint32_t b_addr0 = sbase +
        (uint32_t)(((wn + brow) * KPAD + bkof) * 2);

    const int QK = K / 4;

    for (int b = blockIdx.x; b < 2 * n_tiles; b += gridDim.x) {
        const int t = b >> 1;
        const int r0 = t * MTILE;

        __syncthreads();
        if (tid < MTILE) gid_s[tid] = batch_idx[r0 + tid];
        __syncthreads();

        #pragma unroll
        for (int base = 0; base < NITER; base += 4) {
            float4 v[4];
            #pragma unroll
            for (int i = 0; i < 4; i++) {
                int j = tid + (base + i) * 256;
                int r = j / QK, q = j % QK;
                v[i] = *(const float4*)(A_gmem + (size_t)(r0 + r) * K + q * 4);
            }
            #pragma unroll
            for (int i = 0; i < 4; i++) {
                int j = tid + (base + i) * 256;
                int r = j / QK, q = j % QK;
                __nv_bfloat162 p0 = __float22bfloat162_rn(make_float2(v[i].x, v[i].y));
                __nv_bfloat162 p1 = __float22bfloat162_rn(make_float2(v[i].z, v[i].w));
                *(__nv_bfloat162*)&As[r * KPAD + q * 4]     = p0;
                *(__nv_bfloat162*)&As[r * KPAD + q * 4 + 2] = p1;
            }
        }
        __syncthreads();

        int gr0[2], gr1[2];
        #pragma unroll
        for (int mf = 0; mf < 2; mf++) {
            gr0[mf] = gid_s[wm + mf * 16 + gID];
            gr1[mf] = gid_s[wm + mf * 16 + gID + 8];
        }
        const int g_lo = gid_s[0];
        const int g_hi = gid_s[MTILE - 1];

        float c[2][4][4];
        #pragma unroll
        for (int mf = 0; mf < 2; mf++)
            #pragma unroll
            for (int nf = 0; nf < 4; nf++)
                #pragma unroll
                for (int r = 0; r < 4; r++) c[mf][nf][r] = 0.f;

        #pragma unroll
        for (int ks = 0; ks < KSTEPS; ks++) {
            const uint32_t koff = (uint32_t)(ks * 16 * 2);
            uint32_t a[2][4];
            LDSM_X4(a[0][0], a[0][1], a[0][2], a[0][3], a_addr0 + koff);
            LDSM_X4(a[1][0], a[1][1], a[1][2], a[1][3], a_addr1 + koff);
            #pragma unroll
            for (int nfp = 0; nfp < 2; nfp++) {
                uint32_t b0, b1, b2, b3;
                LDSM_X4(b0, b1, b2, b3,
                        b_addr0 + (uint32_t)(nfp * 16 * KPAD * 2) + koff);
                const int nf = 2 * nfp;
                MMA16816(c[0][nf][0], c[0][nf][1], c[0][nf][2], c[0][nf][3],
                         a[0][0], a[0][1], a[0][2], a[0][3], b0, b1);
                MMA16816(c[1][nf][0], c[1][nf][1], c[1][nf][2], c[1][nf][3],
                         a[1][0], a[1][1], a[1][2], a[1][3], b0, b1);
                MMA16816(c[0][nf+1][0], c[0][nf+1][1], c[0][nf+1][2], c[0][nf+1][3],
                         a[0][0], a[0][1], a[0][2], a[0][3], b2, b3);
                MMA16816(c[1][nf+1][0], c[1][nf+1][1], c[1][nf+1][2], c[1][nf+1][3],
                         a[1][0], a[1][1], a[1][2], a[1][3], b2, b3);
            }
        }

        #pragma unroll
        for (int nf = 0; nf < 4; nf++) {
            float b0 = bias_s[wn + nf * 8 + 2 * tig];
            float b1 = bias_s[wn + nf * 8 + 2 * tig + 1];
            #pragma unroll
            for (int mf = 0; mf < 2; mf++) {
                c[mf][nf][0] = fmaxf(c[mf][nf][0] + b0, 0.f);
                c[mf][nf][1] = fmaxf(c[mf][nf][1] + b1, 0.f);
                c[mf][nf][2] = fmaxf(c[mf][nf][2] + b0, 0.f);
                c[mf][nf][3] = fmaxf(c[mf][nf][3] + b1, 0.f);
            }
        }

        for (int g = g_lo; g <= g_hi; ++g) {
            #pragma unroll
            for (int nf = 0; nf < 4; nf++) {
                float s0 = 0.f, s1 = 0.f;
                #pragma unroll
                for (int mf = 0; mf < 2; mf++) {
                    if (gr0[mf] == g) { s0 += c[mf][nf][0]; s1 += c[mf][nf][1]; }
                    if (gr1[mf] == g) { s0 += c[mf][nf][2]; s1 += c[mf][nf][3]; }
                }
                #pragma unroll
                for (int o = 4; o <= 16; o <<= 1) {
                    s0 += __shfl_xor_sync(0xffffffffu, s0, o);
                    s1 += __shfl_xor_sync(0xffffffffu, s1, o);
                }
                if (lane < 4) {
                    float* dst = &S_out[g * HDIM + nbase + wn + nf * 8 + 2 * lane];
                    atomicAdd(dst,     s0);
                    atomicAdd(dst + 1, s1);
                }
            }
        }
    }
}

#define SMEM_NODE ((NCTA + MTILE) * (D_NODE + 8) * 2 + 1024)   // 53248

__global__ void __launch_bounds__(256, 4)
k_gemm_node(const float* __restrict__ x, const int* __restrict__ batch_idx,
            const float* __restrict__ bn1)
{
    extern __shared__ char smem[];
    uint32_t sbase = (uint32_t)__cvta_generic_to_shared(smem);
    node_gemm_phase<D_NODE, D_NODE + 8, D_NODE / 16, MTILE * (D_NODE / 4) / 256>(
        x, bn1, d_Wt_node, batch_idx, NODE_TILES, d_S_node, smem, sbase);
}

// ---------------- launch #6: means -> layer-2 -> combine ------------------
__global__ void __launch_bounds__(256)
k_finalize(const float* __restrict__ Wn2, const float* __restrict__ bn2,
           const float* __restrict__ We2, const float* __restrict__ be2,
           const float* __restrict__ Wc,  const float* __restrict__ bc,
           float* __restrict__ out)
{
    __shared__ float mn[8][HDIM], me[8][HDIM], gr[8][HDIM];
    __shared__ int fn[8], fe[8];
    const int tid = threadIdx.x;
    const int gbase = blockIdx.x * 8;

    #pragma unroll
    for (int gg = 0; gg < 8; gg++) {
        int g = gbase + gg;
        int cn = d_cnt_node[g], ce = d_cnt_edge[g];
        if (tid == 0) { fn[gg] = cn; fe[gg] = ce; }
        mn[gg][tid] = (cn > 0) ? d_S_node[g * HDIM + tid] / (float)cn : 0.f;
        me[gg][tid] = (ce > 0) ? d_S_edge[g * HDIM + tid] / (float)ce : 0.f;
    }
    __syncthreads();

    float an[8], ae[8];
    #pragma unroll
    for (int gg = 0; gg < 8; gg++) { an[gg] = 0.f; ae[gg] = 0.f; }
    for (int j = 0; j < HDIM; j++) {
        float w1 = Wn2[j * HDIM + tid];
        float w2 = We2[j * HDIM + tid];
        #pragma unroll
        for (int gg = 0; gg < 8; gg++) {
            an[gg] += mn[gg][j] * w1;
            ae[gg] += me[gg][j] * w2;
        }
    }
    float b2n = bn2[tid], b2e = be2[tid];
    #pragma unroll
    for (int gg = 0; gg < 8; gg++) {
        float nr = (fn[gg] > 0) ? an[gg] + b2n : 0.f;
        float er = (fe[gg] > 0) ? ae[gg] + b2e : 0.f;
        gr[gg][tid] = nr + er;
    }
    __syncthreads();

    float ao[8];
    #pragma unroll
    for (int gg = 0; gg < 8; gg++) ao[gg] = 0.f;
    for (int j = 0; j < HDIM; j++) {
        float w = Wc[j * HDIM + tid];
        #pragma unroll
        for (int gg = 0; gg < 8; gg++) ao[gg] += gr[gg][j] * w;
    }
    float bcv = bc[tid];
    #pragma unroll
    for (int gg = 0; gg < 8; gg++)
        out[(gbase + gg) * HDIM + tid] = ao[gg] + bcv;
}

// ---------------- launch ----------------
extern "C" void kernel_launch(void* const* d_in, const int* in_sizes, int n_in,
                              void* d_out, int out_size)
{
    const float* x         = (const float*)d_in[0];
    const float* edge_attr = (const float*)d_in[1];
    const int*   batch_idx = (const int*)d_in[2];
    const int*   edge_src  = (const int*)d_in[3];
    const float* Wn1 = (const float*)d_in[4];
    const float* bn1 = (const float*)d_in[5];
    const float* Wn2 = (const float*)d_in[6];
    const float* bn2 = (const float*)d_in[7];
    const float* We1 = (const float*)d_in[8];
    const float* be1 = (const float*)d_in[9];
    const float* We2 = (const float*)d_in[10];
    const float* be2 = (const float*)d_in[11];
    const float* Wc  = (const float*)d_in[12];
    const float* bc  = (const float*)d_in[13];
    float* out = (float*)d_out;

    (void)in_sizes; (void)n_in; (void)out_size;

    cudaFuncSetAttribute(k_gemm_node, cudaFuncAttributeMaxDynamicSharedMemorySize, SMEM_NODE);
    cudaFuncSetAttribute(k_gemm_edge, cudaFuncAttributeMaxDynamicSharedMemorySize, E_SMEM);

    // zero the histogram counters before k_setup's atomics
    void* p_cn = nullptr; void* p_ce = nullptr;
    cudaGetSymbolAddress(&p_cn, d_cnt_node);
    cudaGetSymbolAddress(&p_ce, d_cnt_edge);
    cudaMemsetAsync(p_cn, 0, NGRAPH * sizeof(int));
    cudaMemsetAsync(p_ce, 0, NGRAPH * sizeof(int));

    k_setup<<<840, 256>>>(Wn1, We1, batch_idx, edge_src);              // kernel #1
    k_scan<<<1, 512>>>();                                              // #2
    k_scatter<<<512, 256>>>();                                         // #3
    k_gemm_edge<<<444, 256, E_SMEM>>>(edge_attr, be1);                 // #4 (profiled slot)
    k_gemm_node<<<592, 256, SMEM_NODE>>>(x, batch_idx, bn1);           // #5
    k_finalize<<<64, 256>>>(Wn2, bn2, We2, be2, Wc, bc, out);          // #6
}